// round 15
// baseline (speedup 1.0000x reference)
#include <cuda_runtime.h>
#include <cuda_fp16.h>
#include <cstdint>

// Problem dims (fixed)
#define BB   2
#define SS   64
#define CIN  16
#define HID  32
#define COUT 128
#define HH   64
#define WW   64
#define NN   (BB*SS)      // 128
#define HWELEMS (HH*WW)   // 4096

// scratch plane A: [n][hid][hw] packed half2(f', i'*g)   (67 MB)
// scratch plane B: [n][hid][hw] half sigmoid(o)          (33.5 MB)
__device__ uint32_t scA[(size_t)NN * HID * HWELEMS];
__device__ __half   scB[(size_t)NN * HID * HWELEMS];

// x tile: [6 rows][66 cols][24 halves(16 ci + 8 pad)] -> uint32 words
#define XT_COL_W   12                 // words per col (24 halves)
#define XT_ROW_W   (66 * XT_COL_W)    // 792
#define XT_WORDS   (6 * XT_ROW_W)     // 4752 words = 19008 B
// weights: [64 lc][152 halves(144 k + 8 pad)] -> 76 words per lc
#define WS_LC_W    76
#define WS_WORDS   (64 * WS_LC_W)     // 4864 words = 19456 B
// dynamic smem: xt[2] | ws | bias
#define SMEM_DYN   ((2 * XT_WORDS + WS_WORDS) * 4 + 256)   // 57728

__device__ __forceinline__ void mma_f16(float* d, const uint32_t* a, const uint32_t* b) {
    asm volatile(
        "mma.sync.aligned.m16n8k16.row.col.f32.f16.f16.f32 "
        "{%0,%1,%2,%3}, {%4,%5,%6,%7}, {%8,%9}, {%0,%1,%2,%3};"
        : "+f"(d[0]), "+f"(d[1]), "+f"(d[2]), "+f"(d[3])
        : "r"(a[0]), "r"(a[1]), "r"(a[2]), "r"(a[3]), "r"(b[0]), "r"(b[1]));
}
__device__ __forceinline__ void ldsm_x4(uint32_t* r, uint32_t saddr) {
    asm volatile("ldmatrix.sync.aligned.m8n8.x4.shared.b16 {%0,%1,%2,%3}, [%4];"
        : "=r"(r[0]), "=r"(r[1]), "=r"(r[2]), "=r"(r[3]) : "r"(saddr));
}
__device__ __forceinline__ uint32_t smem_u32(const void* p) {
    uint32_t a;
    asm("{ .reg .u64 t; cvta.to.shared.u64 t, %1; cvt.u32.u64 %0, t; }"
        : "=r"(a) : "l"(p));
    return a;
}
__device__ __forceinline__ uint32_t pack_h2(float lo, float hi) {
    __half2 h = __floats2half2_rn(lo, hi);
    return *reinterpret_cast<uint32_t*>(&h);
}

// Load one x-tile position (row,col) as 8 packed fp16x2 words (16 ci).
__device__ __forceinline__ void load_pos(const float* __restrict__ xn, int h0,
                                         int pidx, uint32_t* pr) {
    const int row = pidx / 66;
    const int col = pidx - row * 66;
    const int gr = h0 - 1 + row;
    const int gc = col - 1;
    if ((unsigned)gr < HH && (unsigned)gc < WW) {
        const float* src = xn + gr * WW + gc;
        #pragma unroll
        for (int j = 0; j < 8; j++)
            pr[j] = pack_h2(__ldg(src + (2 * j) * HWELEMS),
                            __ldg(src + (2 * j + 1) * HWELEMS));
    } else {
        #pragma unroll
        for (int j = 0; j < 8; j++) pr[j] = 0u;
    }
}
__device__ __forceinline__ void sts_pos(uint32_t* xtb, int pidx, const uint32_t* pr) {
    const int row = pidx / 66;
    const int col = pidx - row * 66;
    uint32_t* dst = xtb + row * XT_ROW_W + col * XT_COL_W;
    *(uint4*)(dst)     = make_uint4(pr[0], pr[1], pr[2], pr[3]);
    *(uint4*)(dst + 4) = make_uint4(pr[4], pr[5], pr[6], pr[7]);
}

// ---------------------------------------------------------------------------
// fp16 implicit-GEMM conv + in-register gate epilogue (R11 config, best
// measured), parameterized by batch half: units v in [half*1024, half*1024+1024)
// (i.e. images n in [half*64, half*64+64)).
// CTA: 256 thr, M=256 px (4 rows x 64 w) x N=64 co (co-half q = grid parity).
// ---------------------------------------------------------------------------
__global__ void __launch_bounds__(256, 2)
conv_gates_mma_kernel(const float* __restrict__ x,
                      const float* __restrict__ Wt,
                      const float* __restrict__ bias,
                      int half)
{
    extern __shared__ uint32_t smw[];
    uint32_t* xt0 = smw;
    uint32_t* xt1 = smw + XT_WORDS;
    uint32_t* ws  = smw + 2 * XT_WORDS;
    float*    bsp = (float*)(smw + 2 * XT_WORDS + WS_WORDS);

    const int tid  = threadIdx.x;
    const int lane = tid & 31;
    const int wid  = tid >> 5;
    const int gid  = lane >> 2;     // 0..7
    const int tig  = lane & 3;      // 0..3
    const int wm   = wid & 3;       // spatial row within 4-row tile
    const int wn   = wid >> 2;      // channel group (8 chans)

    const int q    = blockIdx.x & 1;    // co-half: hid chans q*16..q*16+15
    const int uid  = blockIdx.x >> 1;   // 0..147
    const int vbase = half << 10;       // 1024 units per batch half

    // ---- stage weights as fp16 pairs: ws[lc][k], lc = g*16 + chan_local ----
    for (int i = tid; i < 64 * 72; i += 256) {
        int lc = i / 72, kw2 = i - lc * 72;
        int k0 = kw2 * 2;
        int cc = k0 >> 4, ci = k0 & 15;
        int co = ((lc >> 4) << 5) + (q << 4) + (lc & 15);
        float v0 = __ldg(&Wt[(co * 16 + ci)     * 9 + cc]);
        float v1 = __ldg(&Wt[(co * 16 + ci + 1) * 9 + cc]);
        ws[lc * WS_LC_W + kw2] = pack_h2(v0, v1);
    }
    if (tid < 64)
        bsp[tid] = bias[((tid >> 4) << 5) + (q << 4) + (tid & 15)];

    const int cl0 = wn * 8 + tig * 2;   // chan_local for even accum cols

    // ldmatrix per-lane address components (byte offsets)
    const int pxr   = (lane & 7) + ((lane >> 3) & 1) * 8;
    const int awoff = ((lane >> 4) & 1) * 4;
    const uint32_t aoff = (uint32_t)(pxr * XT_COL_W + awoff) * 4;
    const int bg    = (lane >> 4);
    const int bwoff = ((lane >> 3) & 1) * 4;
    const uint32_t boff = (uint32_t)(((bg << 4) + (wn << 3) + (lane & 7)) * WS_LC_W + bwoff) * 4;

    const uint32_t xt0_u = smem_u32(xt0);
    const uint32_t xt1_u = smem_u32(xt1);
    const uint32_t ws_u  = smem_u32(ws);

    // ---- prologue: load first tile into xt0 ----
    {
        const int v0i = vbase + uid;
        const float* xn = x + (size_t)(v0i >> 4) * CIN * HWELEMS;
        const int h0 = (v0i & 15) << 2;
        uint32_t pr[8];
        load_pos(xn, h0, tid, pr);
        sts_pos(xt0, tid, pr);
        if (tid + 256 < 396) {
            load_pos(xn, h0, tid + 256, pr);
            sts_pos(xt0, tid + 256, pr);
        }
    }
    __syncthreads();

    int buf = 0;
    for (int u = uid; u < 1024; u += 148) {
        const int v  = vbase + u;
        const int n  = v >> 4;
        const int h0 = (v & 15) << 2;
        const int un = u + 148;
        const bool nx = (un < 1024);

        // ---- issue next-tile loads into registers (hidden under MMA) ----
        uint32_t pr0[8], pr1[8];
        if (nx) {
            const int v2 = vbase + un;
            const float* xn2 = x + (size_t)(v2 >> 4) * CIN * HWELEMS;
            const int h02 = (v2 & 15) << 2;
            load_pos(xn2, h02, tid, pr0);
            if (tid + 256 < 396) load_pos(xn2, h02, tid + 256, pr1);
        }

        const uint32_t xb_u = buf ? xt1_u : xt0_u;
        uint32_t* xnb       = buf ? xt0 : xt1;

        // ---- GEMM mainloop: 9 taps, k16 per tap ----
        float acc[4][4][4];   // [mf][gate][frag]
        #pragma unroll
        for (int mf = 0; mf < 4; mf++)
            #pragma unroll
            for (int g = 0; g < 4; g++)
                #pragma unroll
                for (int e = 0; e < 4; e++) acc[mf][g][e] = 0.0f;

        #pragma unroll
        for (int cc = 0; cc < 9; cc++) {
            const int kh = cc / 3;
            const int kw = cc - kh * 3;
            uint32_t bf[4][2];
            {
                const uint32_t bbase = ws_u + boff + (uint32_t)(cc << 5);
                uint32_t r01[4], r23[4];
                ldsm_x4(r01, bbase);
                ldsm_x4(r23, bbase + 32u * WS_LC_W * 4u);
                bf[0][0] = r01[0]; bf[0][1] = r01[1];
                bf[1][0] = r01[2]; bf[1][1] = r01[3];
                bf[2][0] = r23[0]; bf[2][1] = r23[1];
                bf[3][0] = r23[2]; bf[3][1] = r23[3];
            }
            const uint32_t abase = xb_u + aoff
                + (uint32_t)((wm + kh) * XT_ROW_W + kw * XT_COL_W) * 4;
            #pragma unroll
            for (int mf = 0; mf < 4; mf++) {
                uint32_t af[4];
                ldsm_x4(af, abase + (uint32_t)(mf * 16 * XT_COL_W) * 4);
                #pragma unroll
                for (int g = 0; g < 4; g++)
                    mma_f16(acc[mf][g], af, bf[g]);
            }
        }

        // ---- store next tile to back buffer (frees pipeline regs) ----
        if (nx) {
            sts_pos(xnb, tid, pr0);
            if (tid + 256 < 396) sts_pos(xnb, tid + 256, pr1);
        }

        // ---- in-register gate epilogue -> fp16 scratch planes ----
        const int h = h0 + wm;
        const float bI0 = bsp[cl0],      bI1 = bsp[cl0 + 1];
        const float bF0 = bsp[16 + cl0], bF1 = bsp[16 + cl0 + 1];
        const float bO0 = bsp[32 + cl0], bO1 = bsp[32 + cl0 + 1];
        const float bC0 = bsp[48 + cl0], bC1 = bsp[48 + cl0 + 1];
        #pragma unroll
        for (int mf = 0; mf < 4; mf++) {
            #pragma unroll
            for (int eh = 0; eh < 2; eh++) {
                const int w = mf * 16 + gid + eh * 8;
                #pragma unroll
                for (int ec = 0; ec < 2; ec++) {
                    const int e = eh * 2 + ec;
                    float iv = acc[mf][0][e] + (ec ? bI1 : bI0);
                    float fv = acc[mf][1][e] + (ec ? bF1 : bF0);
                    float ov = acc[mf][2][e] + (ec ? bO1 : bO0);
                    float cv = acc[mf][3][e] + (ec ? bC1 : bC0);
                    float ei  = __expf(-iv);
                    float ef  = __expf(-fv);
                    float inv = __fdividef(1.f, 2.f + ei + ef);
                    float fp  = (1.f + ei) * inv;                   // f'
                    float ip  = 1.f - fp;                           // i' (exact)
                    float g   = (cv >= 0.f) ? (cv + 0.5f)
                              : __fdividef(1.f, 1.f + __expf(-cv));
                    float so  = __fdividef(1.f, 1.f + __expf(-ov));
                    const int chan = (q << 4) + cl0 + ec;
                    size_t idx = ((size_t)n * HID + chan) * HWELEMS
                                 + (size_t)h * WW + w;
                    scA[idx] = pack_h2(fp, ip * g);
                    scB[idx] = __float2half_rn(so);
                }
            }
        }

        __syncthreads();   // STS to back buffer visible before next MMA
        buf ^= 1;
    }
}

// ---------------------------------------------------------------------------
// Scan for ONE batch: streaming recurrence on fp16 gate planes,
// 2 hw per thread (best-measured load width), 256 blocks per batch.
// ---------------------------------------------------------------------------
__global__ void __launch_bounds__(256)
lstm_scan_kernel(const float* __restrict__ c0,
                 float* __restrict__ out,
                 float* __restrict__ clast,
                 int b)
{
    const int t  = blockIdx.x * blockDim.x + threadIdx.x;   // 0..65535
    const int hw = (t & 2047) << 1;
    const int ch = t >> 11;                                  // 0..31

    float2 cs = *(const float2*)&c0[((size_t)b * HID + ch) * HWELEMS + hw];
    const size_t ST = (size_t)HID * HWELEMS;     // per-timestep stride
    size_t idx = ((size_t)(b * SS) * HID + ch) * HWELEMS + hw;
    const uint32_t* pA = scA + idx;
    const __half*   pB = scB + idx;
    float* op = out + idx;

    #pragma unroll 4
    for (int s = 0; s < SS; s++) {
        uint2 a = *(const uint2*)pA;
        __half2 sb = *(const __half2*)pB;
        float2 v0 = __half22float2(*reinterpret_cast<__half2*>(&a.x)); // (f', ig)
        float2 v1 = __half22float2(*reinterpret_cast<__half2*>(&a.y));
        float2 so = __half22float2(sb);
        cs.x = fmaf(v0.x, cs.x, v0.y);
        cs.y = fmaf(v1.x, cs.y, v1.y);
        *(float2*)op = make_float2(so.x * cs.x, so.y * cs.y);
        pA += ST;
        pB += ST;
        op += ST;
    }
    *(float2*)&clast[((size_t)b * HID + ch) * HWELEMS + hw] = cs;
}

// ---------------------------------------------------------------------------
// Launch graph:  conv(b=0) -> { conv(b=1) on main  ||  scan(b=0) on side }
//                -> scan(b=1).
// Stream/event creation happens only on the few real host invocations
// (correctness run + capture); replays execute the captured graph.
// ---------------------------------------------------------------------------
extern "C" void kernel_launch(void* const* d_in, const int* in_sizes, int n_in,
                              void* d_out, int out_size)
{
    const float* x  = (const float*)d_in[0];   // (2,64,16,64,64)
    const float* Wt = (const float*)d_in[1];   // (128,16,3,3)
    const float* b  = (const float*)d_in[2];   // (128)
    const float* c0 = (const float*)d_in[3];   // (2,1,32,64,64)

    float* out   = (float*)d_out;                              // (2,64,32,64,64)
    float* clast = out + (size_t)BB * SS * HID * HWELEMS;      // (2,1,32,64,64)

    cudaFuncSetAttribute(conv_gates_mma_kernel,
                         cudaFuncAttributeMaxDynamicSharedMemorySize, SMEM_DYN);

    cudaStream_t s2;
    cudaEvent_t evFork, evJoin;
    cudaStreamCreateWithFlags(&s2, cudaStreamNonBlocking);
    cudaEventCreateWithFlags(&evFork, cudaEventDisableTiming);
    cudaEventCreateWithFlags(&evJoin, cudaEventDisableTiming);

    // phase 1: conv for batch 0 (main stream)
    conv_gates_mma_kernel<<<296, 256, SMEM_DYN>>>(x, Wt, b, 0);

    // fork: side stream joins the capture after conv0
    cudaEventRecord(evFork, 0);
    cudaStreamWaitEvent(s2, evFork, 0);

    // phase 2: conv batch 1 (main)  ||  scan batch 0 (side)
    conv_gates_mma_kernel<<<296, 256, SMEM_DYN>>>(x, Wt, b, 1);
    lstm_scan_kernel<<<256, 256, 0, s2>>>(c0, out, clast, 0);

    // join: main stream waits for scan0 (conv1 already ordered on main)
    cudaEventRecord(evJoin, s2);
    cudaStreamWaitEvent(0, evJoin, 0);

    // phase 3: scan batch 1 (main)
    lstm_scan_kernel<<<256, 256>>>(c0, out, clast, 1);
}

// round 16
// speedup vs baseline: 1.0433x; 1.0433x over previous
#include <cuda_runtime.h>
#include <cuda_fp16.h>
#include <cstdint>

// Problem dims (fixed)
#define BB   2
#define SS   64
#define CIN  16
#define HID  32
#define COUT 128
#define HH   64
#define WW   64
#define NN   (BB*SS)      // 128
#define HWELEMS (HH*WW)   // 4096

// scratch plane A: [n][hid][hw] packed half2(f', i'*g)   (67 MB)
// scratch plane B: [n][hid][hw] half sigmoid(o)          (33.5 MB)
__device__ uint32_t scA[(size_t)NN * HID * HWELEMS];
__device__ __half   scB[(size_t)NN * HID * HWELEMS];

// x tile: [6 rows][66 cols][24 halves(16 ci + 8 pad)] -> uint32 words
#define XT_COL_W   12                 // words per col (24 halves)
#define XT_ROW_W   (66 * XT_COL_W)    // 792
#define XT_WORDS   (6 * XT_ROW_W)     // 4752 words = 19008 B
// weights: [64 lc][152 halves(144 k + 8 pad)] -> 76 words per lc
#define WS_LC_W    76
#define WS_WORDS   (64 * WS_LC_W)     // 4864 words = 19456 B
// dynamic smem: xt[2] | ws | bias
#define SMEM_DYN   ((2 * XT_WORDS + WS_WORDS) * 4 + 256)   // 57728

__device__ __forceinline__ void mma_f16(float* d, const uint32_t* a, const uint32_t* b) {
    asm volatile(
        "mma.sync.aligned.m16n8k16.row.col.f32.f16.f16.f32 "
        "{%0,%1,%2,%3}, {%4,%5,%6,%7}, {%8,%9}, {%0,%1,%2,%3};"
        : "+f"(d[0]), "+f"(d[1]), "+f"(d[2]), "+f"(d[3])
        : "r"(a[0]), "r"(a[1]), "r"(a[2]), "r"(a[3]), "r"(b[0]), "r"(b[1]));
}
__device__ __forceinline__ void ldsm_x4(uint32_t* r, uint32_t saddr) {
    asm volatile("ldmatrix.sync.aligned.m8n8.x4.shared.b16 {%0,%1,%2,%3}, [%4];"
        : "=r"(r[0]), "=r"(r[1]), "=r"(r[2]), "=r"(r[3]) : "r"(saddr));
}
__device__ __forceinline__ uint32_t smem_u32(const void* p) {
    uint32_t a;
    asm("{ .reg .u64 t; cvta.to.shared.u64 t, %1; cvt.u32.u64 %0, t; }"
        : "=r"(a) : "l"(p));
    return a;
}
__device__ __forceinline__ uint32_t pack_h2(float lo, float hi) {
    __half2 h = __floats2half2_rn(lo, hi);
    return *reinterpret_cast<uint32_t*>(&h);
}
// streaming (evict-first) stores for single-use scratch
__device__ __forceinline__ void stcs_u32(uint32_t* p, uint32_t v) {
    asm volatile("st.global.cs.u32 [%0], %1;" :: "l"(p), "r"(v) : "memory");
}
__device__ __forceinline__ void stcs_u16(__half* p, uint32_t v) {
    asm volatile("st.global.cs.u16 [%0], %1;" :: "l"(p), "r"(v) : "memory");
}

// Load one x-tile position (row,col) as 8 packed fp16x2 words (16 ci).
__device__ __forceinline__ void load_pos(const float* __restrict__ xn, int h0,
                                         int pidx, uint32_t* pr) {
    const int row = pidx / 66;
    const int col = pidx - row * 66;
    const int gr = h0 - 1 + row;
    const int gc = col - 1;
    if ((unsigned)gr < HH && (unsigned)gc < WW) {
        const float* src = xn + gr * WW + gc;
        #pragma unroll
        for (int j = 0; j < 8; j++)
            pr[j] = pack_h2(__ldg(src + (2 * j) * HWELEMS),
                            __ldg(src + (2 * j + 1) * HWELEMS));
    } else {
        #pragma unroll
        for (int j = 0; j < 8; j++) pr[j] = 0u;
    }
}
__device__ __forceinline__ void sts_pos(uint32_t* xtb, int pidx, const uint32_t* pr) {
    const int row = pidx / 66;
    const int col = pidx - row * 66;
    uint32_t* dst = xtb + row * XT_ROW_W + col * XT_COL_W;
    *(uint4*)(dst)     = make_uint4(pr[0], pr[1], pr[2], pr[3]);
    *(uint4*)(dst + 4) = make_uint4(pr[4], pr[5], pr[6], pr[7]);
}

// ---------------------------------------------------------------------------
// fp16 implicit-GEMM conv + in-register gate epilogue (R11 configuration —
// best measured). CTA: 256 thr, M=256 px (4 rows x 64 w) x N=64 co (half q).
// Warps 4(m) x 2(n); warp N-tile = 4 gates x 8 chans -> gates fused in regs.
// ldmatrix fragment feeds, software-pipelined x-tile loads, 2 CTAs/SM.
// Scratch written with .cs (evict-first) to keep x/weights L2-resident.
// ---------------------------------------------------------------------------
__global__ void __launch_bounds__(256, 2)
conv_gates_mma_kernel(const float* __restrict__ x,
                      const float* __restrict__ Wt,
                      const float* __restrict__ bias)
{
    extern __shared__ uint32_t smw[];
    uint32_t* xt0 = smw;
    uint32_t* xt1 = smw + XT_WORDS;
    uint32_t* ws  = smw + 2 * XT_WORDS;
    float*    bsp = (float*)(smw + 2 * XT_WORDS + WS_WORDS);

    const int tid  = threadIdx.x;
    const int lane = tid & 31;
    const int wid  = tid >> 5;
    const int gid  = lane >> 2;     // 0..7
    const int tig  = lane & 3;      // 0..3
    const int wm   = wid & 3;       // spatial row within 4-row tile
    const int wn   = wid >> 2;      // channel group (8 chans)

    const int q   = blockIdx.x & 1;    // co-half: hid chans q*16..q*16+15
    const int uid = blockIdx.x >> 1;   // 0..147

    // ---- stage weights as fp16 pairs: ws[lc][k], lc = g*16 + chan_local ----
    for (int i = tid; i < 64 * 72; i += 256) {
        int lc = i / 72, kw2 = i - lc * 72;
        int k0 = kw2 * 2;
        int cc = k0 >> 4, ci = k0 & 15;
        int co = ((lc >> 4) << 5) + (q << 4) + (lc & 15);
        float v0 = __ldg(&Wt[(co * 16 + ci)     * 9 + cc]);
        float v1 = __ldg(&Wt[(co * 16 + ci + 1) * 9 + cc]);
        ws[lc * WS_LC_W + kw2] = pack_h2(v0, v1);
    }
    if (tid < 64)
        bsp[tid] = bias[((tid >> 4) << 5) + (q << 4) + (tid & 15)];

    const int cl0 = wn * 8 + tig * 2;   // chan_local for even accum cols

    // ldmatrix per-lane address components (byte offsets)
    const int pxr   = (lane & 7) + ((lane >> 3) & 1) * 8;
    const int awoff = ((lane >> 4) & 1) * 4;
    const uint32_t aoff = (uint32_t)(pxr * XT_COL_W + awoff) * 4;
    const int bg    = (lane >> 4);
    const int bwoff = ((lane >> 3) & 1) * 4;
    const uint32_t boff = (uint32_t)(((bg << 4) + (wn << 3) + (lane & 7)) * WS_LC_W + bwoff) * 4;

    const uint32_t xt0_u = smem_u32(xt0);
    const uint32_t xt1_u = smem_u32(xt1);
    const uint32_t ws_u  = smem_u32(ws);

    // ---- prologue: load first tile into xt0 ----
    {
        const float* xn = x + (size_t)(uid >> 4) * CIN * HWELEMS;
        const int h0 = (uid & 15) << 2;
        uint32_t pr[8];
        load_pos(xn, h0, tid, pr);
        sts_pos(xt0, tid, pr);
        if (tid + 256 < 396) {
            load_pos(xn, h0, tid + 256, pr);
            sts_pos(xt0, tid + 256, pr);
        }
    }
    __syncthreads();

    int buf = 0;
    for (int u = uid; u < 2048; u += 148) {
        const int n  = u >> 4;
        const int h0 = (u & 15) << 2;
        const int un = u + 148;
        const bool nx = (un < 2048);

        // ---- issue next-tile loads into registers (hidden under MMA) ----
        uint32_t pr0[8], pr1[8];
        if (nx) {
            const float* xn2 = x + (size_t)(un >> 4) * CIN * HWELEMS;
            const int h02 = (un & 15) << 2;
            load_pos(xn2, h02, tid, pr0);
            if (tid + 256 < 396) load_pos(xn2, h02, tid + 256, pr1);
        }

        const uint32_t xb_u = buf ? xt1_u : xt0_u;
        uint32_t* xnb       = buf ? xt0 : xt1;

        // ---- GEMM mainloop: 9 taps, k16 per tap ----
        float acc[4][4][4];   // [mf][gate][frag]
        #pragma unroll
        for (int mf = 0; mf < 4; mf++)
            #pragma unroll
            for (int g = 0; g < 4; g++)
                #pragma unroll
                for (int e = 0; e < 4; e++) acc[mf][g][e] = 0.0f;

        #pragma unroll
        for (int cc = 0; cc < 9; cc++) {
            const int kh = cc / 3;
            const int kw = cc - kh * 3;
            uint32_t bf[4][2];
            {
                const uint32_t bbase = ws_u + boff + (uint32_t)(cc << 5);
                uint32_t r01[4], r23[4];
                ldsm_x4(r01, bbase);
                ldsm_x4(r23, bbase + 32u * WS_LC_W * 4u);
                bf[0][0] = r01[0]; bf[0][1] = r01[1];
                bf[1][0] = r01[2]; bf[1][1] = r01[3];
                bf[2][0] = r23[0]; bf[2][1] = r23[1];
                bf[3][0] = r23[2]; bf[3][1] = r23[3];
            }
            const uint32_t abase = xb_u + aoff
                + (uint32_t)((wm + kh) * XT_ROW_W + kw * XT_COL_W) * 4;
            #pragma unroll
            for (int mf = 0; mf < 4; mf++) {
                uint32_t af[4];
                ldsm_x4(af, abase + (uint32_t)(mf * 16 * XT_COL_W) * 4);
                #pragma unroll
                for (int g = 0; g < 4; g++)
                    mma_f16(acc[mf][g], af, bf[g]);
            }
        }

        // ---- store next tile to back buffer (frees pipeline regs) ----
        if (nx) {
            sts_pos(xnb, tid, pr0);
            if (tid + 256 < 396) sts_pos(xnb, tid + 256, pr1);
        }

        // ---- in-register gate epilogue -> fp16 scratch planes (.cs) ----
        const int h = h0 + wm;
        const float bI0 = bsp[cl0],      bI1 = bsp[cl0 + 1];
        const float bF0 = bsp[16 + cl0], bF1 = bsp[16 + cl0 + 1];
        const float bO0 = bsp[32 + cl0], bO1 = bsp[32 + cl0 + 1];
        const float bC0 = bsp[48 + cl0], bC1 = bsp[48 + cl0 + 1];
        #pragma unroll
        for (int mf = 0; mf < 4; mf++) {
            #pragma unroll
            for (int eh = 0; eh < 2; eh++) {
                const int w = mf * 16 + gid + eh * 8;
                #pragma unroll
                for (int ec = 0; ec < 2; ec++) {
                    const int e = eh * 2 + ec;
                    float iv = acc[mf][0][e] + (ec ? bI1 : bI0);
                    float fv = acc[mf][1][e] + (ec ? bF1 : bF0);
                    float ov = acc[mf][2][e] + (ec ? bO1 : bO0);
                    float cv = acc[mf][3][e] + (ec ? bC1 : bC0);
                    float ei  = __expf(-iv);
                    float ef  = __expf(-fv);
                    float inv = __fdividef(1.f, 2.f + ei + ef);
                    float fp  = (1.f + ei) * inv;                   // f'
                    float ip  = 1.f - fp;                           // i' (exact)
                    float g   = (cv >= 0.f) ? (cv + 0.5f)
                              : __fdividef(1.f, 1.f + __expf(-cv));
                    float so  = __fdividef(1.f, 1.f + __expf(-ov));
                    const int chan = (q << 4) + cl0 + ec;
                    size_t idx = ((size_t)n * HID + chan) * HWELEMS
                                 + (size_t)h * WW + w;
                    stcs_u32(&scA[idx], pack_h2(fp, ip * g));
                    uint32_t sob;
                    { __half hs = __float2half_rn(so);
                      sob = (uint32_t)*reinterpret_cast<unsigned short*>(&hs); }
                    stcs_u16(&scB[idx], sob);
                }
            }
        }

        __syncthreads();   // STS to back buffer visible before next MMA
        buf ^= 1;
    }
}

// ---------------------------------------------------------------------------
// Scan: streaming recurrence on fp16 gate planes, 2 sequences per thread
// (best-measured width). All streams read once -> .cs loads / .cs out store.
// ---------------------------------------------------------------------------
__global__ void __launch_bounds__(256)
lstm_scan_kernel(const float* __restrict__ c0,
                 float* __restrict__ out,
                 float* __restrict__ clast)
{
    const int t  = blockIdx.x * blockDim.x + threadIdx.x;   // 0..131071
    const int hw = (t & 2047) << 1;
    const int ch = (t >> 11) & 31;
    const int b  = t >> 16;

    float2 cs = *(const float2*)&c0[((size_t)b * HID + ch) * HWELEMS + hw];
    const size_t ST = (size_t)HID * HWELEMS;     // per-timestep stride
    size_t idx = ((size_t)(b * SS) * HID + ch) * HWELEMS + hw;
    const uint32_t* pA = scA + idx;
    const uint32_t* pB = (const uint32_t*)(scB + idx);   // hw even -> 4B aligned
    float* op = out + idx;

    #pragma unroll 4
    for (int s = 0; s < SS; s++) {
        uint2 a = __ldcs((const uint2*)pA);
        uint32_t sbw = __ldcs(pB);
        float2 v0 = __half22float2(*reinterpret_cast<__half2*>(&a.x)); // (f', ig)
        float2 v1 = __half22float2(*reinterpret_cast<__half2*>(&a.y));
        float2 so = __half22float2(*reinterpret_cast<__half2*>(&sbw));
        cs.x = fmaf(v0.x, cs.x, v0.y);
        cs.y = fmaf(v1.x, cs.y, v1.y);
        float2 ov = make_float2(so.x * cs.x, so.y * cs.y);
        __stcs((float2*)op, ov);
        pA += ST;
        pB += ST / 2;          // half-plane stride in u32 words
        op += ST;
    }
    *(float2*)&clast[((size_t)b * HID + ch) * HWELEMS + hw] = cs;
}

// ---------------------------------------------------------------------------
extern "C" void kernel_launch(void* const* d_in, const int* in_sizes, int n_in,
                              void* d_out, int out_size)
{
    const float* x  = (const float*)d_in[0];   // (2,64,16,64,64)
    const float* Wt = (const float*)d_in[1];   // (128,16,3,3)
    const float* b  = (const float*)d_in[2];   // (128)
    const float* c0 = (const float*)d_in[3];   // (2,1,32,64,64)

    float* out   = (float*)d_out;                              // (2,64,32,64,64)
    float* clast = out + (size_t)BB * SS * HID * HWELEMS;      // (2,1,32,64,64)

    cudaFuncSetAttribute(conv_gates_mma_kernel,
                         cudaFuncAttributeMaxDynamicSharedMemorySize, SMEM_DYN);

    conv_gates_mma_kernel<<<296, 256, SMEM_DYN>>>(x, Wt, b);

    const int total2 = BB * HID * HWELEMS / 2;   // 131072
    lstm_scan_kernel<<<total2 / 256, 256>>>(c0, out, clast);
}

// round 17
// speedup vs baseline: 1.1544x; 1.1065x over previous
#include <cuda_runtime.h>
#include <cuda_fp16.h>
#include <cstdint>

// Problem dims (fixed)
#define BB   2
#define SS   64
#define CIN  16
#define HID  32
#define COUT 128
#define HH   64
#define WW   64
#define NN   (BB*SS)      // 128
#define HWELEMS (HH*WW)   // 4096

// scratch plane A: [n][hid][hw] packed half2(f', i'*g)   (67 MB)
// scratch plane B: [n][hid][hw] half sigmoid(o)          (33.5 MB)
// Written with DEFAULT cache policy: scratch largely fits in L2, and the
// scan's speed depends on that residency (R16 showed .cs here costs +17us).
__device__ uint32_t scA[(size_t)NN * HID * HWELEMS];
__device__ __half   scB[(size_t)NN * HID * HWELEMS];

// x tile: [6 rows][66 cols][24 halves(16 ci + 8 pad)] -> uint32 words
#define XT_COL_W   12                 // words per col (24 halves)
#define XT_ROW_W   (66 * XT_COL_W)    // 792
#define XT_WORDS   (6 * XT_ROW_W)     // 4752 words = 19008 B
// weights: [64 lc][152 halves(144 k + 8 pad)] -> 76 words per lc
#define WS_LC_W    76
#define WS_WORDS   (64 * WS_LC_W)     // 4864 words = 19456 B
// dynamic smem: xt[2] | ws | bias
#define SMEM_DYN   ((2 * XT_WORDS + WS_WORDS) * 4 + 256)   // 57728

__device__ __forceinline__ void mma_f16(float* d, const uint32_t* a, const uint32_t* b) {
    asm volatile(
        "mma.sync.aligned.m16n8k16.row.col.f32.f16.f16.f32 "
        "{%0,%1,%2,%3}, {%4,%5,%6,%7}, {%8,%9}, {%0,%1,%2,%3};"
        : "+f"(d[0]), "+f"(d[1]), "+f"(d[2]), "+f"(d[3])
        : "r"(a[0]), "r"(a[1]), "r"(a[2]), "r"(a[3]), "r"(b[0]), "r"(b[1]));
}
__device__ __forceinline__ void ldsm_x4(uint32_t* r, uint32_t saddr) {
    asm volatile("ldmatrix.sync.aligned.m8n8.x4.shared.b16 {%0,%1,%2,%3}, [%4];"
        : "=r"(r[0]), "=r"(r[1]), "=r"(r[2]), "=r"(r[3]) : "r"(saddr));
}
__device__ __forceinline__ uint32_t smem_u32(const void* p) {
    uint32_t a;
    asm("{ .reg .u64 t; cvta.to.shared.u64 t, %1; cvt.u32.u64 %0, t; }"
        : "=r"(a) : "l"(p));
    return a;
}
__device__ __forceinline__ uint32_t pack_h2(float lo, float hi) {
    __half2 h = __floats2half2_rn(lo, hi);
    return *reinterpret_cast<uint32_t*>(&h);
}

// Load one x-tile position (row,col) as 8 packed fp16x2 words (16 ci).
__device__ __forceinline__ void load_pos(const float* __restrict__ xn, int h0,
                                         int pidx, uint32_t* pr) {
    const int row = pidx / 66;
    const int col = pidx - row * 66;
    const int gr = h0 - 1 + row;
    const int gc = col - 1;
    if ((unsigned)gr < HH && (unsigned)gc < WW) {
        const float* src = xn + gr * WW + gc;
        #pragma unroll
        for (int j = 0; j < 8; j++)
            pr[j] = pack_h2(__ldg(src + (2 * j) * HWELEMS),
                            __ldg(src + (2 * j + 1) * HWELEMS));
    } else {
        #pragma unroll
        for (int j = 0; j < 8; j++) pr[j] = 0u;
    }
}
__device__ __forceinline__ void sts_pos(uint32_t* xtb, int pidx, const uint32_t* pr) {
    const int row = pidx / 66;
    const int col = pidx - row * 66;
    uint32_t* dst = xtb + row * XT_ROW_W + col * XT_COL_W;
    *(uint4*)(dst)     = make_uint4(pr[0], pr[1], pr[2], pr[3]);
    *(uint4*)(dst + 4) = make_uint4(pr[4], pr[5], pr[6], pr[7]);
}

// ---------------------------------------------------------------------------
// fp16 implicit-GEMM conv + in-register gate epilogue (best configuration,
// R11). CTA: 256 thr, M=256 px (4 rows x 64 w) x N=64 co (co-half q).
// Warps 4(m) x 2(n); warp N-tile = 4 gates x 8 chans -> gates fused in regs.
// ldmatrix fragment feeds, software-pipelined x-tile loads, 2 CTAs/SM.
// ---------------------------------------------------------------------------
__global__ void __launch_bounds__(256, 2)
conv_gates_mma_kernel(const float* __restrict__ x,
                      const float* __restrict__ Wt,
                      const float* __restrict__ bias)
{
    extern __shared__ uint32_t smw[];
    uint32_t* xt0 = smw;
    uint32_t* xt1 = smw + XT_WORDS;
    uint32_t* ws  = smw + 2 * XT_WORDS;
    float*    bsp = (float*)(smw + 2 * XT_WORDS + WS_WORDS);

    const int tid  = threadIdx.x;
    const int lane = tid & 31;
    const int wid  = tid >> 5;
    const int gid  = lane >> 2;     // 0..7
    const int tig  = lane & 3;      // 0..3
    const int wm   = wid & 3;       // spatial row within 4-row tile
    const int wn   = wid >> 2;      // channel group (8 chans)

    const int q   = blockIdx.x & 1;    // co-half: hid chans q*16..q*16+15
    const int uid = blockIdx.x >> 1;   // 0..147

    // ---- stage weights as fp16 pairs: ws[lc][k], lc = g*16 + chan_local ----
    for (int i = tid; i < 64 * 72; i += 256) {
        int lc = i / 72, kw2 = i - lc * 72;
        int k0 = kw2 * 2;
        int cc = k0 >> 4, ci = k0 & 15;
        int co = ((lc >> 4) << 5) + (q << 4) + (lc & 15);
        float v0 = __ldg(&Wt[(co * 16 + ci)     * 9 + cc]);
        float v1 = __ldg(&Wt[(co * 16 + ci + 1) * 9 + cc]);
        ws[lc * WS_LC_W + kw2] = pack_h2(v0, v1);
    }
    if (tid < 64)
        bsp[tid] = bias[((tid >> 4) << 5) + (q << 4) + (tid & 15)];

    const int cl0 = wn * 8 + tig * 2;   // chan_local for even accum cols

    // ldmatrix per-lane address components (byte offsets)
    const int pxr   = (lane & 7) + ((lane >> 3) & 1) * 8;
    const int awoff = ((lane >> 4) & 1) * 4;
    const uint32_t aoff = (uint32_t)(pxr * XT_COL_W + awoff) * 4;
    const int bg    = (lane >> 4);
    const int bwoff = ((lane >> 3) & 1) * 4;
    const uint32_t boff = (uint32_t)(((bg << 4) + (wn << 3) + (lane & 7)) * WS_LC_W + bwoff) * 4;

    const uint32_t xt0_u = smem_u32(xt0);
    const uint32_t xt1_u = smem_u32(xt1);
    const uint32_t ws_u  = smem_u32(ws);

    // ---- prologue: load first tile into xt0 ----
    {
        const float* xn = x + (size_t)(uid >> 4) * CIN * HWELEMS;
        const int h0 = (uid & 15) << 2;
        uint32_t pr[8];
        load_pos(xn, h0, tid, pr);
        sts_pos(xt0, tid, pr);
        if (tid + 256 < 396) {
            load_pos(xn, h0, tid + 256, pr);
            sts_pos(xt0, tid + 256, pr);
        }
    }
    __syncthreads();

    int buf = 0;
    for (int u = uid; u < 2048; u += 148) {
        const int n  = u >> 4;
        const int h0 = (u & 15) << 2;
        const int un = u + 148;
        const bool nx = (un < 2048);

        // ---- issue next-tile loads into registers (hidden under MMA) ----
        uint32_t pr0[8], pr1[8];
        if (nx) {
            const float* xn2 = x + (size_t)(un >> 4) * CIN * HWELEMS;
            const int h02 = (un & 15) << 2;
            load_pos(xn2, h02, tid, pr0);
            if (tid + 256 < 396) load_pos(xn2, h02, tid + 256, pr1);
        }

        const uint32_t xb_u = buf ? xt1_u : xt0_u;
        uint32_t* xnb       = buf ? xt0 : xt1;

        // ---- GEMM mainloop: 9 taps, k16 per tap ----
        float acc[4][4][4];   // [mf][gate][frag]
        #pragma unroll
        for (int mf = 0; mf < 4; mf++)
            #pragma unroll
            for (int g = 0; g < 4; g++)
                #pragma unroll
                for (int e = 0; e < 4; e++) acc[mf][g][e] = 0.0f;

        #pragma unroll
        for (int cc = 0; cc < 9; cc++) {
            const int kh = cc / 3;
            const int kw = cc - kh * 3;
            uint32_t bf[4][2];
            {
                const uint32_t bbase = ws_u + boff + (uint32_t)(cc << 5);
                uint32_t r01[4], r23[4];
                ldsm_x4(r01, bbase);
                ldsm_x4(r23, bbase + 32u * WS_LC_W * 4u);
                bf[0][0] = r01[0]; bf[0][1] = r01[1];
                bf[1][0] = r01[2]; bf[1][1] = r01[3];
                bf[2][0] = r23[0]; bf[2][1] = r23[1];
                bf[3][0] = r23[2]; bf[3][1] = r23[3];
            }
            const uint32_t abase = xb_u + aoff
                + (uint32_t)((wm + kh) * XT_ROW_W + kw * XT_COL_W) * 4;
            #pragma unroll
            for (int mf = 0; mf < 4; mf++) {
                uint32_t af[4];
                ldsm_x4(af, abase + (uint32_t)(mf * 16 * XT_COL_W) * 4);
                #pragma unroll
                for (int g = 0; g < 4; g++)
                    mma_f16(acc[mf][g], af, bf[g]);
            }
        }

        // ---- store next tile to back buffer (frees pipeline regs) ----
        if (nx) {
            sts_pos(xnb, tid, pr0);
            if (tid + 256 < 396) sts_pos(xnb, tid + 256, pr1);
        }

        // ---- in-register gate epilogue -> fp16 scratch planes ----
        const int h = h0 + wm;
        const float bI0 = bsp[cl0],      bI1 = bsp[cl0 + 1];
        const float bF0 = bsp[16 + cl0], bF1 = bsp[16 + cl0 + 1];
        const float bO0 = bsp[32 + cl0], bO1 = bsp[32 + cl0 + 1];
        const float bC0 = bsp[48 + cl0], bC1 = bsp[48 + cl0 + 1];
        #pragma unroll
        for (int mf = 0; mf < 4; mf++) {
            #pragma unroll
            for (int eh = 0; eh < 2; eh++) {
                const int w = mf * 16 + gid + eh * 8;
                #pragma unroll
                for (int ec = 0; ec < 2; ec++) {
                    const int e = eh * 2 + ec;
                    float iv = acc[mf][0][e] + (ec ? bI1 : bI0);
                    float fv = acc[mf][1][e] + (ec ? bF1 : bF0);
                    float ov = acc[mf][2][e] + (ec ? bO1 : bO0);
                    float cv = acc[mf][3][e] + (ec ? bC1 : bC0);
                    float ei  = __expf(-iv);
                    float ef  = __expf(-fv);
                    float inv = __fdividef(1.f, 2.f + ei + ef);
                    float fp  = (1.f + ei) * inv;                   // f'
                    float ip  = 1.f - fp;                           // i' (exact)
                    float g   = (cv >= 0.f) ? (cv + 0.5f)
                              : __fdividef(1.f, 1.f + __expf(-cv));
                    float so  = __fdividef(1.f, 1.f + __expf(-ov));
                    const int chan = (q << 4) + cl0 + ec;
                    size_t idx = ((size_t)n * HID + chan) * HWELEMS
                                 + (size_t)h * WW + w;
                    scA[idx] = pack_h2(fp, ip * g);
                    scB[idx] = __float2half_rn(so);
                }
            }
        }

        __syncthreads();   // STS to back buffer visible before next MMA
        buf ^= 1;
    }
}

// ---------------------------------------------------------------------------
// Scan: streaming recurrence on fp16 gate planes, 2 sequences per thread.
// Default cache policy — rides the L2 residency of the scratch (proven 25.7us).
// ---------------------------------------------------------------------------
__global__ void __launch_bounds__(256)
lstm_scan_kernel(const float* __restrict__ c0,
                 float* __restrict__ out,
                 float* __restrict__ clast)
{
    const int t  = blockIdx.x * blockDim.x + threadIdx.x;   // 0..131071
    const int hw = (t & 2047) << 1;
    const int ch = (t >> 11) & 31;
    const int b  = t >> 16;

    float2 cs = *(const float2*)&c0[((size_t)b * HID + ch) * HWELEMS + hw];
    const size_t ST = (size_t)HID * HWELEMS;     // per-timestep stride
    size_t idx = ((size_t)(b * SS) * HID + ch) * HWELEMS + hw;
    const uint32_t* pA = scA + idx;
    const __half*   pB = scB + idx;
    float* op = out + idx;

    #pragma unroll 4
    for (int s = 0; s < SS; s++) {
        uint2 a = *(const uint2*)pA;
        __half2 sb = *(const __half2*)pB;
        float2 v0 = __half22float2(*reinterpret_cast<__half2*>(&a.x)); // (f', ig)
        float2 v1 = __half22float2(*reinterpret_cast<__half2*>(&a.y));
        float2 so = __half22float2(sb);
        cs.x = fmaf(v0.x, cs.x, v0.y);
        cs.y = fmaf(v1.x, cs.y, v1.y);
        *(float2*)op = make_float2(so.x * cs.x, so.y * cs.y);
        pA += ST;
        pB += ST;
        op += ST;
    }
    *(float2*)&clast[((size_t)b * HID + ch) * HWELEMS + hw] = cs;
}

// ---------------------------------------------------------------------------
extern "C" void kernel_launch(void* const* d_in, const int* in_sizes, int n_in,
                              void* d_out, int out_size)
{
    const float* x  = (const float*)d_in[0];   // (2,64,16,64,64)
    const float* Wt = (const float*)d_in[1];   // (128,16,3,3)
    const float* b  = (const float*)d_in[2];   // (128)
    const float* c0 = (const float*)d_in[3];   // (2,1,32,64,64)

    float* out   = (float*)d_out;                              // (2,64,32,64,64)
    float* clast = out + (size_t)BB * SS * HID * HWELEMS;      // (2,1,32,64,64)

    cudaFuncSetAttribute(conv_gates_mma_kernel,
                         cudaFuncAttributeMaxDynamicSharedMemorySize, SMEM_DYN);

    conv_gates_mma_kernel<<<296, 256, SMEM_DYN>>>(x, Wt, b);

    const int total2 = BB * HID * HWELEMS / 2;   // 131072
    lstm_scan_kernel<<<total2 / 256, 256>>>(c0, out, clast);
}